// round 1
// baseline (speedup 1.0000x reference)
#include <cuda_runtime.h>

// LRN with all-ones CxCx5x5 filter:
//   s[b,h,w]  = sum_c x[b,c,h,w]^2
//   y[b,h,w]  = 5x5 zero-padded box sum of s
//   out       = x * (2 + 1e-4*y)^(-0.75)
//
// Shapes: x [16, 96, 224, 224] fp32.

#define BATCH 16
#define CHAN  96
#define HH    224
#define WW    224
#define HWSZ  (HH * WW)            // 50176
#define CHW   (CHAN * HWSZ)        // 4816896
#define TOT   (BATCH * CHW)        // 77070336

#define K_CONST 2.0f
#define ALPHA   1e-4f
#define BETA    0.75f

// Scratch (no cudaMalloc allowed): channel-sum-of-squares and final scale factor.
__device__ float g_s[BATCH * HWSZ];
__device__ float g_f[BATCH * HWSZ];

// ---------------------------------------------------------------------------
// Kernel A: s[b,hw] = sum_c x[b,c,hw]^2    (float4 over spatial)
// ---------------------------------------------------------------------------
__global__ void __launch_bounds__(256) chan_sumsq_kernel(const float* __restrict__ x) {
    int i4 = blockIdx.x * blockDim.x + threadIdx.x;      // float4 index over B*HW/4
    const int n4 = (BATCH * HWSZ) / 4;
    if (i4 >= n4) return;

    int e  = i4 * 4;
    int b  = e / HWSZ;
    int hw = e - b * HWSZ;

    const float4* xp = reinterpret_cast<const float4*>(x + (size_t)b * CHW + hw);
    float4 acc = make_float4(0.f, 0.f, 0.f, 0.f);

#pragma unroll 4
    for (int c = 0; c < CHAN; ++c) {
        float4 v = __ldg(&xp[c * (HWSZ / 4)]);
        acc.x = fmaf(v.x, v.x, acc.x);
        acc.y = fmaf(v.y, v.y, acc.y);
        acc.z = fmaf(v.z, v.z, acc.z);
        acc.w = fmaf(v.w, v.w, acc.w);
    }
    reinterpret_cast<float4*>(g_s)[i4] = acc;
}

// ---------------------------------------------------------------------------
// Kernel B: f[b,hw] = (2 + 1e-4 * boxsum5x5(s))^(-0.75)   (zero padding)
// Tiny tensor (3.2 MB) -> naive per-pixel 25-tap read, L1/L2 resident.
// ---------------------------------------------------------------------------
__global__ void __launch_bounds__(256) box_factor_kernel() {
    int i = blockIdx.x * blockDim.x + threadIdx.x;
    if (i >= BATCH * HWSZ) return;

    int b  = i / HWSZ;
    int hw = i - b * HWSZ;
    int h  = hw / WW;
    int w  = hw - h * WW;

    const float* sp = g_s + b * HWSZ;
    float t = 0.f;
#pragma unroll
    for (int dh = -2; dh <= 2; ++dh) {
        int hh = h + dh;
        if ((unsigned)hh >= (unsigned)HH) continue;
        const float* row = sp + hh * WW;
#pragma unroll
        for (int dw = -2; dw <= 2; ++dw) {
            int ww2 = w + dw;
            if ((unsigned)ww2 >= (unsigned)WW) continue;
            t += __ldg(&row[ww2]);
        }
    }
    float base = fmaf(ALPHA, t, K_CONST);           // in [2, ~3.5] for N(0,1) input
    g_f[i] = exp2f(-BETA * log2f(base));
}

// ---------------------------------------------------------------------------
// Kernel C: out = x * f[b,hw]   (float4; f broadcast over channels)
// ---------------------------------------------------------------------------
__global__ void __launch_bounds__(256) scale_kernel(const float* __restrict__ x,
                                                    float* __restrict__ out) {
    int i4 = blockIdx.x * blockDim.x + threadIdx.x;      // float4 index over TOT/4
    const int n4 = TOT / 4;
    if (i4 >= n4) return;

    int e   = i4 * 4;
    int b   = e / CHW;
    int rem = e - b * CHW;
    int hw  = rem % HWSZ;                                // multiple of 4 (HWSZ % 4 == 0)

    float4 xv = reinterpret_cast<const float4*>(x)[i4];
    float4 fv = *reinterpret_cast<const float4*>(g_f + b * HWSZ + hw);

    float4 o;
    o.x = xv.x * fv.x;
    o.y = xv.y * fv.y;
    o.z = xv.z * fv.z;
    o.w = xv.w * fv.w;
    reinterpret_cast<float4*>(out)[i4] = o;
}

// ---------------------------------------------------------------------------
extern "C" void kernel_launch(void* const* d_in, const int* in_sizes, int n_in,
                              void* d_out, int out_size) {
    const float* x = (const float*)d_in[0];
    float* out = (float*)d_out;

    {
        int n4 = (BATCH * HWSZ) / 4;                     // 200704
        int threads = 256;
        int blocks = (n4 + threads - 1) / threads;
        chan_sumsq_kernel<<<blocks, threads>>>(x);
    }
    {
        int n = BATCH * HWSZ;                            // 802816
        int threads = 256;
        int blocks = (n + threads - 1) / threads;
        box_factor_kernel<<<blocks, threads>>>();
    }
    {
        int n4 = TOT / 4;                                // 19267584
        int threads = 256;
        int blocks = (n4 + threads - 1) / threads;
        scale_kernel<<<blocks, threads>>>(x, out);
    }
}